// round 16
// baseline (speedup 1.0000x reference)
#include <cuda_runtime.h>
#include <cstdint>

// diff[K, N, D] = x[None, :, :] - centroid[:, None, :]
// N=65536, K=32, D=64, fp32. Store-roofline: 536 MB out.
// Converged SM-side config: KG=4, THREADS=256, __stcs -> 76.3us (7.0 TB/s).
//
// Store PATH probe (R15 retry, fixed missing <cstdint>): stage each CTA's
// 4 output tiles (4 KB each) in SMEM, emit via cp.async.bulk (TMA bulk
// store) — writes reach L2/DRAM as 4 KB single-burst transfers instead of
// per-warp 32B sectors. Same LTS cap (path-independent) but potentially
// better DRAM write-row batching.

#define N_PTS 65536
#define K_CENT 32
#define D_DIM 64
#define D4 (D_DIM / 4)            // 16 float4 per row
#define KG 4                      // k's per CTA (optimum)
#define KY (K_CENT / KG)          // gridDim.y = 8
#define CENT_F4 (KG * D4)         // 64 float4 = 1 KB centroids
#define THREADS 256

__global__ void __launch_bounds__(THREADS, 8)
kmeans_diff_kernel(const float4* __restrict__ x,
                   const float4* __restrict__ cent,
                   float4* __restrict__ out) {
    __shared__ float4 sc[CENT_F4];
    __shared__ __align__(128) float4 tile[KG * THREADS];  // 16 KB staging

    const int k0 = blockIdx.y * KG;

    for (int i = threadIdx.x; i < CENT_F4; i += blockDim.x)
        sc[i] = cent[k0 * D4 + i];
    __syncthreads();

    const unsigned idx = blockIdx.x * THREADS + threadIdx.x;  // [0, N*D/4)
    const unsigned d4 = idx & (D4 - 1);

    const float4 xv = x[idx];

    // Compute all KG results into SMEM staging (layout matches gmem order).
#pragma unroll
    for (int kk = 0; kk < KG; kk++) {
        const float4 c = sc[kk * D4 + d4];
        float4 r;
        r.x = xv.x - c.x;
        r.y = xv.y - c.y;
        r.z = xv.z - c.z;
        r.w = xv.w - c.w;
        tile[kk * THREADS + threadIdx.x] = r;
    }

    // Order generic-proxy SMEM writes before async-proxy bulk reads.
    asm volatile("fence.proxy.async.shared::cta;" ::: "memory");
    __syncthreads();

    // One thread emits KG bulk stores: 4 KB contiguous burst per plane.
    if (threadIdx.x == 0) {
        const size_t plane = (size_t)N_PTS * D4;
        const unsigned blk_base = blockIdx.x * THREADS;

        unsigned int smem_addr;
        asm("{ .reg .u64 t; cvta.to.shared.u64 t, %1; cvt.u32.u64 %0, t; }"
            : "=r"(smem_addr) : "l"(tile));

#pragma unroll
        for (int kk = 0; kk < KG; kk++) {
            const float4* dst = out + ((size_t)(k0 + kk)) * plane + blk_base;
            asm volatile(
                "cp.async.bulk.global.shared::cta.bulk_group [%0], [%1], %2;"
                :: "l"(dst),
                   "r"(smem_addr + kk * THREADS * 16),
                   "r"(THREADS * 16)
                : "memory");
        }
        asm volatile("cp.async.bulk.commit_group;" ::: "memory");
        asm volatile("cp.async.bulk.wait_group 0;" ::: "memory");
    }
}

extern "C" void kernel_launch(void* const* d_in, const int* in_sizes, int n_in,
                              void* d_out, int out_size) {
    const float4* x    = (const float4*)d_in[0];   // [N, D] fp32
    const float4* cent = (const float4*)d_in[1];   // [K, D] fp32
    float4* out        = (float4*)d_out;           // [K, N, D] fp32

    const int total_f4 = N_PTS * D4;               // 1,048,576
    dim3 grid(total_f4 / THREADS, KY);             // (4096, 8)
    kmeans_diff_kernel<<<grid, THREADS>>>(x, cent, out);
}

// round 17
// speedup vs baseline: 1.2115x; 1.2115x over previous
#include <cuda_runtime.h>

// diff[K, N, D] = x[None, :, :] - centroid[:, None, :]
// N=65536, K=32, D=64, fp32. Pure store-roofline problem: 536 MB out.
//
// FINAL — converged optimum after 16-round exhaustive axis sweep (GB300):
//   write streams KG: 32->81.9  8->78.0  4->76.3(min)  2->77.1
//   per-thread ILP:   1 (ILP=2 regressed at every KG tested)
//   store policy:     __stcs (default 92.9 = L2 dirty thrash;
//                     .wt 94.2 = loses LTS coalescing)
//   store path:       STG.cs (TMA cp.async.bulk 92.4 — no .cs hint on the
//                     bulk path -> same dirty-thrash class + SMEM round-trip)
//   CTA size:         256 (512 tie); chunking: none (88.6); prefetch: none (79.9)
//
// Common thread of all failures: losing evict-first L2 policy on the 536 MB
// write stream costs ~16us. 76.3us = 7.03 TB/s = 88% of HBM spec; residual
// is DRAM write-turnaround physics, non-addressable from the SM.

#define N_PTS 65536
#define K_CENT 32
#define D_DIM 64
#define D4 (D_DIM / 4)            // 16 float4 per row
#define KG 4                      // k's per CTA (optimum)
#define KY (K_CENT / KG)          // gridDim.y = 8
#define CENT_F4 (KG * D4)         // 64 float4 = 1 KB staged per CTA
#define THREADS 256

__global__ void __launch_bounds__(THREADS, 8)
kmeans_diff_kernel(const float4* __restrict__ x,
                   const float4* __restrict__ cent,
                   float4* __restrict__ out) {
    __shared__ float4 sc[CENT_F4];

    const int k0 = blockIdx.y * KG;

    // Stage this CTA's KG centroid rows (1 KB) into shared.
    for (int i = threadIdx.x; i < CENT_F4; i += blockDim.x)
        sc[i] = cent[k0 * D4 + i];
    __syncthreads();

    const unsigned idx = blockIdx.x * THREADS + threadIdx.x;  // [0, N*D/4)
    const unsigned d4 = idx & (D4 - 1);

    const float4 xv = x[idx];  // DRAM first wave, L2 hit afterwards

    const size_t plane = (size_t)N_PTS * D4;  // float4 per k-plane
    float4* o = out + (size_t)k0 * plane + idx;

#pragma unroll
    for (int kk = 0; kk < KG; kk++) {
        const float4 c = sc[kk * D4 + d4];
        float4 r;
        r.x = xv.x - c.x;
        r.y = xv.y - c.y;
        r.z = xv.z - c.z;
        r.w = xv.w - c.w;
        __stcs(o, r);            // evict-first: the load-bearing optimization
        o += plane;
    }
}

extern "C" void kernel_launch(void* const* d_in, const int* in_sizes, int n_in,
                              void* d_out, int out_size) {
    const float4* x    = (const float4*)d_in[0];   // [N, D] fp32
    const float4* cent = (const float4*)d_in[1];   // [K, D] fp32
    float4* out        = (float4*)d_out;           // [K, N, D] fp32

    const int total_f4 = N_PTS * D4;               // 1,048,576
    dim3 grid(total_f4 / THREADS, KY);             // (4096, 8)
    kmeans_diff_kernel<<<grid, THREADS>>>(x, cent, out);
}